// round 3
// baseline (speedup 1.0000x reference)
#include <cuda_runtime.h>

// RLFrameSelector: scores = relu(x@W1 + b1)@W2 + b2, mask invalid frames,
// top-k per batch row, output x * selection.
// Shapes fixed: B=32, T=2048, F=512, U=128, M = B*T = 65536.

#define NEG_BIG -1.0e9f

__device__ float g_scores[65536];
__device__ unsigned char g_flags[65536];

__device__ __forceinline__ void fma2(unsigned long long &d,
                                     unsigned long long a,
                                     unsigned long long b) {
    asm("fma.rn.f32x2 %0, %1, %2, %0;" : "+l"(d) : "l"(a), "l"(b));
}
__device__ __forceinline__ unsigned long long dup2(float a) {
    unsigned long long r;
    unsigned int u = __float_as_uint(a);
    asm("mov.b64 %0, {%1, %1};" : "=l"(r) : "r"(u));
    return r;
}
__device__ __forceinline__ void unpack2(unsigned long long v, float &lo, float &hi) {
    unsigned int a, b;
    asm("mov.b64 {%0, %1}, %2;" : "=r"(a), "=r"(b) : "l"(v));
    lo = __uint_as_float(a);
    hi = __uint_as_float(b);
}

// ---------------------------------------------------------------------------
// Kernel A: fused GEMM1 + relu + GEMM2 + mask -> g_scores
// CTA: 128 frames x 128 U, 256 threads, 8x8 microtile per thread via f32x2.
// ---------------------------------------------------------------------------
__global__ __launch_bounds__(256, 2) void score_kernel(
    const float* __restrict__ x, const float* __restrict__ W1,
    const float* __restrict__ b1, const float* __restrict__ W2,
    const float* __restrict__ b2)
{
    __shared__ float xs[128][33];   // x tile [m][k], padded
    __shared__ float ws[32][128];   // W1 tile [k][u]
    __shared__ float sW2[128];
    __shared__ float sB1[128];
    __shared__ unsigned char rowflag[128];
    __shared__ float red[128][17];  // score reduction scratch

    const int tid = threadIdx.x;
    const int tx = tid & 15;        // U groups (16 x 8 = 128)
    const int ty = tid >> 4;        // M groups (16 x 8 = 128)
    const int bm0 = blockIdx.x << 7;

    if (tid < 128) {
        rowflag[tid] = 0;
        sW2[tid] = W2[tid];
        sB1[tid] = b1[tid];
    }

    unsigned long long acc[8][4];
#pragma unroll
    for (int i = 0; i < 8; i++)
#pragma unroll
        for (int j = 0; j < 4; j++) acc[i][j] = 0ULL;

    const float4* xg = (const float4*)x;

    for (int kc = 0; kc < 512; kc += 32) {
        __syncthreads();
        // --- load x tile: 128 rows x 32 floats = 1024 float4 ---
        const float4* wg = (const float4*)(W1 + kc * 128);
#pragma unroll
        for (int p = 0; p < 4; p++) {
            int idx = tid + p * 256;
            int r = idx >> 3, c4 = idx & 7;
            float4 v = xg[(bm0 + r) * 128 + (kc >> 2) + c4];
            if (v.x != 0.f || v.y != 0.f || v.z != 0.f || v.w != 0.f)
                rowflag[r] = 1;  // idempotent, races benign
            xs[r][c4 * 4 + 0] = v.x;
            xs[r][c4 * 4 + 1] = v.y;
            xs[r][c4 * 4 + 2] = v.z;
            xs[r][c4 * 4 + 3] = v.w;
        }
        // --- load W1 tile: 32 rows x 128 floats = 1024 float4 ---
#pragma unroll
        for (int p = 0; p < 4; p++) {
            int idx = tid + p * 256;
            int kr = idx >> 5, u4 = idx & 31;
            ((float4*)(&ws[kr][0]))[u4] = wg[kr * 32 + u4];
        }
        __syncthreads();
        // --- compute ---
#pragma unroll 8
        for (int kk = 0; kk < 32; kk++) {
            const ulonglong2* bp = (const ulonglong2*)(&ws[kk][tx * 8]);
            ulonglong2 q0 = bp[0];
            ulonglong2 q1 = bp[1];
            unsigned long long bx0 = q0.x, bx1 = q0.y, bx2 = q1.x, bx3 = q1.y;
#pragma unroll
            for (int i = 0; i < 8; i++) {
                unsigned long long ax = dup2(xs[ty * 8 + i][kk]);
                fma2(acc[i][0], ax, bx0);
                fma2(acc[i][1], ax, bx1);
                fma2(acc[i][2], ax, bx2);
                fma2(acc[i][3], ax, bx3);
            }
        }
    }
    __syncthreads();

    // --- epilogue: relu, dot with W2, reduce across tx ---
#pragma unroll
    for (int i = 0; i < 8; i++) {
        float p = 0.f;
#pragma unroll
        for (int j = 0; j < 4; j++) {
            float f0, f1;
            unpack2(acc[i][j], f0, f1);
            int u = tx * 8 + 2 * j;
            float h0 = fmaxf(f0 + sB1[u], 0.f);
            float h1 = fmaxf(f1 + sB1[u + 1], 0.f);
            p += h0 * sW2[u] + h1 * sW2[u + 1];
        }
        red[ty * 8 + i][tx] = p;
    }
    __syncthreads();
    if (tid < 128) {
        float s = 0.f;
#pragma unroll
        for (int t = 0; t < 16; t++) s += red[tid][t];
        s += b2[0];
        g_scores[bm0 + tid] = rowflag[tid] ? s : NEG_BIG;
    }
}

// ---------------------------------------------------------------------------
// Kernel B: exact top-k per batch row via bitonic sort of (score, ~index)
// keys. Ties (only possible at NEG_BIG) resolve to smaller index, matching
// jax.lax.top_k. One CTA per row, 1024 threads, 2048 keys in smem.
// ---------------------------------------------------------------------------
__global__ void topk_kernel(const int* kptr) {
    __shared__ unsigned long long sk[2048];
    const int row = blockIdx.x;
    const int tid = threadIdx.x;
    const float* sc = g_scores + row * 2048;

#pragma unroll
    for (int s = 0; s < 2; s++) {
        int t = tid + s * 1024;
        unsigned int u = __float_as_uint(sc[t]);
        u = (u & 0x80000000u) ? ~u : (u | 0x80000000u);  // order-preserving map
        sk[t] = ((unsigned long long)u << 32) | (unsigned long long)(~(unsigned int)t);
        g_flags[row * 2048 + t] = 0;
    }
    __syncthreads();

    for (int k = 2; k <= 2048; k <<= 1) {
        for (int j = k >> 1; j > 0; j >>= 1) {
#pragma unroll
            for (int s = 0; s < 2; s++) {
                int i = tid + s * 1024;
                int l = i ^ j;
                if (l > i) {
                    unsigned long long a = sk[i], b = sk[l];
                    bool up = ((i & k) == 0);
                    if ((a > b) == up) { sk[i] = b; sk[l] = a; }
                }
            }
            __syncthreads();
        }
    }

    int kk = (kptr != nullptr) ? kptr[0] : 64;
    if (kk < 1) kk = 1;
    if (kk > 2048) kk = 2048;
#pragma unroll
    for (int s = 0; s < 2; s++) {
        int i = tid + s * 1024;
        if (i >= 2048 - kk) {
            unsigned int t = ~(unsigned int)(sk[i] & 0xFFFFFFFFull);
            g_flags[row * 2048 + t] = 1;
        }
    }
}

// ---------------------------------------------------------------------------
// Kernel C: out[frame] = flag ? x[frame] : 0. Reads x only for selected
// frames (~3% of 128 MB); always writes (d_out is poisoned).
// ---------------------------------------------------------------------------
__global__ void output_kernel(const float* __restrict__ x,
                              float* __restrict__ out) {
    const int frame = blockIdx.x;
    const int f = threadIdx.x;  // 128 threads, one float4 each
    float4 v = make_float4(0.f, 0.f, 0.f, 0.f);
    if (g_flags[frame]) v = ((const float4*)x)[frame * 128 + f];
    ((float4*)out)[frame * 128 + f] = v;
}

extern "C" void kernel_launch(void* const* d_in, const int* in_sizes, int n_in,
                              void* d_out, int out_size) {
    const float* x  = (const float*)d_in[0];
    const float* W1 = (const float*)d_in[1];
    const float* b1 = (const float*)d_in[2];
    const float* W2 = (const float*)d_in[3];
    const float* b2 = (const float*)d_in[4];
    const int* kptr = (n_in >= 6) ? (const int*)d_in[5] : nullptr;

    score_kernel<<<512, 256>>>(x, W1, b1, W2, b2);
    topk_kernel<<<32, 1024>>>(kptr);
    output_kernel<<<65536, 128>>>(x, (float*)d_out);
}

// round 4
// speedup vs baseline: 1.1430x; 1.1430x over previous
#include <cuda_runtime.h>

// RLFrameSelector: scores = relu(x@W1 + b1)@W2 + b2, mask invalid frames,
// top-k per batch row, output x * selection.
// Shapes fixed: B=32, T=2048, F=512, U=128, M = B*T = 65536.

#define NEG_BIG -1.0e9f

__device__ float g_scores[65536];
__device__ unsigned char g_flags[65536];

__device__ __forceinline__ void fma2(unsigned long long &d,
                                     unsigned long long a,
                                     unsigned long long b) {
    asm("fma.rn.f32x2 %0, %1, %2, %0;" : "+l"(d) : "l"(a), "l"(b));
}
__device__ __forceinline__ unsigned long long dup2(float a) {
    unsigned long long r;
    unsigned int u = __float_as_uint(a);
    asm("mov.b64 %0, {%1, %1};" : "=l"(r) : "r"(u));
    return r;
}
__device__ __forceinline__ void unpack2(unsigned long long v, float &lo, float &hi) {
    unsigned int a, b;
    asm("mov.b64 {%0, %1}, %2;" : "=r"(a), "=r"(b) : "l"(v));
    lo = __uint_as_float(a);
    hi = __uint_as_float(b);
}
__device__ __forceinline__ unsigned smem_u32(const void* p) {
    return (unsigned)__cvta_generic_to_shared(p);
}
__device__ __forceinline__ void cp_async16(unsigned dst, const void* src) {
    asm volatile("cp.async.cg.shared.global [%0], [%1], 16;" :: "r"(dst), "l"(src));
}

// Dynamic smem layout (bytes):
//   xs  [2][128][36] float : 0      .. 36864   (row pad 36 keeps 16B align)
//   ws  [2][32][128] float : 36864  .. 69632
//   sW2 [128]        float : 69632  .. 70144
//   sB1 [128]        float : 70144  .. 70656
//   nzf [128][16]    uchar : 70656  .. 72704
//   red [128][17]    float : 72704  .. 81408
#define XS_OFF   0
#define WS_OFF   36864
#define SW2_OFF  69632
#define SB1_OFF  70144
#define NZF_OFF  70656
#define RED_OFF  72704
#define SMEM_BYTES 81408

// ---------------------------------------------------------------------------
// Kernel A: fused GEMM1 + relu + GEMM2 + mask -> g_scores
// CTA: 128 frames x 128 U, 256 threads, 8x8 microtile per thread via f32x2.
// cp.async double-buffered global->smem; zero-row mask detected from exact
// +0 accumulator bits in the epilogue (0*w FMA chains stay bitwise +0).
// ---------------------------------------------------------------------------
__global__ __launch_bounds__(256, 2) void score_kernel(
    const float* __restrict__ x, const float* __restrict__ W1,
    const float* __restrict__ b1, const float* __restrict__ W2,
    const float* __restrict__ b2)
{
    extern __shared__ char sm[];
    float* xs = (float*)(sm + XS_OFF);                 // [2][128][36]
    float* ws = (float*)(sm + WS_OFF);                 // [2][32][128]
    float* sW2 = (float*)(sm + SW2_OFF);
    float* sB1 = (float*)(sm + SB1_OFF);
    unsigned char* nzf = (unsigned char*)(sm + NZF_OFF); // [128][16]
    float* red = (float*)(sm + RED_OFF);               // [128][17]

    const int tid = threadIdx.x;
    const int tx = tid & 15;        // U groups (16 x 8 = 128)
    const int ty = tid >> 4;        // M groups (16 x 8 = 128)
    const int bm0 = blockIdx.x << 7;

    if (tid < 128) {
        sW2[tid] = W2[tid];
        sB1[tid] = b1[tid];
    }

    unsigned long long acc[8][4];
#pragma unroll
    for (int i = 0; i < 8; i++)
#pragma unroll
        for (int j = 0; j < 4; j++) acc[i][j] = 0ULL;

    const float4* xg = (const float4*)x;
    const float4* wg4 = (const float4*)W1;

    auto issue_tile = [&](int it, int buf) {
        float* xb = xs + buf * 4608;   // 128*36
        float* wb = ws + buf * 4096;   // 32*128
#pragma unroll
        for (int p = 0; p < 4; p++) {
            int idx = tid + p * 256;
            int r = idx >> 3, c4 = idx & 7;
            cp_async16(smem_u32(xb + r * 36 + c4 * 4),
                       xg + (bm0 + r) * 128 + it * 8 + c4);
        }
#pragma unroll
        for (int p = 0; p < 4; p++) {
            int idx = tid + p * 256;
            int kr = idx >> 5, u4 = idx & 31;
            cp_async16(smem_u32(wb + kr * 128 + u4 * 4),
                       wg4 + it * 1024 + kr * 32 + u4);
        }
        asm volatile("cp.async.commit_group;" ::: "memory");
    };

    issue_tile(0, 0);

    for (int it = 0; it < 16; it++) {
        if (it + 1 < 16) {
            issue_tile(it + 1, (it + 1) & 1);
            asm volatile("cp.async.wait_group 1;" ::: "memory");
        } else {
            asm volatile("cp.async.wait_group 0;" ::: "memory");
        }
        __syncthreads();

        const float* xb = xs + (it & 1) * 4608;
        const float* wb = ws + (it & 1) * 4096;
#pragma unroll 8
        for (int kk = 0; kk < 32; kk++) {
            const ulonglong2* bp = (const ulonglong2*)(wb + kk * 128 + tx * 8);
            ulonglong2 q0 = bp[0];
            ulonglong2 q1 = bp[1];
            unsigned long long bx0 = q0.x, bx1 = q0.y, bx2 = q1.x, bx3 = q1.y;
#pragma unroll
            for (int i = 0; i < 8; i++) {
                unsigned long long ax = dup2(xb[(ty * 8 + i) * 36 + kk]);
                fma2(acc[i][0], ax, bx0);
                fma2(acc[i][1], ax, bx1);
                fma2(acc[i][2], ax, bx2);
                fma2(acc[i][3], ax, bx3);
            }
        }
        __syncthreads();   // protect buffer before next-next issue overwrites
    }

    // --- epilogue: relu, dot with W2, partial reduce + zero-row flags ---
#pragma unroll
    for (int i = 0; i < 8; i++) {
        float p = 0.f;
        unsigned long long ored = acc[i][0] | acc[i][1] | acc[i][2] | acc[i][3];
#pragma unroll
        for (int j = 0; j < 4; j++) {
            float f0, f1;
            unpack2(acc[i][j], f0, f1);
            int u = tx * 8 + 2 * j;
            float h0 = fmaxf(f0 + sB1[u], 0.f);
            float h1 = fmaxf(f1 + sB1[u + 1], 0.f);
            p += h0 * sW2[u] + h1 * sW2[u + 1];
        }
        int m = ty * 8 + i;
        red[m * 17 + tx] = p;
        nzf[m * 16 + tx] = (ored != 0ULL);
    }
    __syncthreads();
    if (tid < 128) {
        float s = 0.f;
        unsigned char nz = 0;
#pragma unroll
        for (int t = 0; t < 16; t++) {
            s += red[tid * 17 + t];
            nz |= nzf[tid * 16 + t];
        }
        g_scores[bm0 + tid] = nz ? (s + b2[0]) : NEG_BIG;
    }
}

// ---------------------------------------------------------------------------
// Kernel B: exact top-k per batch row via bitonic sort of (score, ~index)
// keys. Ties resolve to smaller index, matching jax.lax.top_k selection set.
// One CTA per row, 1024 threads, 2048 keys in smem.
// ---------------------------------------------------------------------------
__global__ void topk_kernel(const int* kptr) {
    __shared__ unsigned long long sk[2048];
    const int row = blockIdx.x;
    const int tid = threadIdx.x;
    const float* sc = g_scores + row * 2048;

#pragma unroll
    for (int s = 0; s < 2; s++) {
        int t = tid + s * 1024;
        unsigned int u = __float_as_uint(sc[t]);
        u = (u & 0x80000000u) ? ~u : (u | 0x80000000u);  // order-preserving map
        sk[t] = ((unsigned long long)u << 32) | (unsigned long long)(~(unsigned int)t);
        g_flags[row * 2048 + t] = 0;
    }
    __syncthreads();

    for (int k = 2; k <= 2048; k <<= 1) {
        for (int j = k >> 1; j > 0; j >>= 1) {
#pragma unroll
            for (int s = 0; s < 2; s++) {
                int i = tid + s * 1024;
                int l = i ^ j;
                if (l > i) {
                    unsigned long long a = sk[i], b = sk[l];
                    bool up = ((i & k) == 0);
                    if ((a > b) == up) { sk[i] = b; sk[l] = a; }
                }
            }
            __syncthreads();
        }
    }

    int kk = (kptr != nullptr) ? kptr[0] : 64;
    if (kk < 1) kk = 1;
    if (kk > 2048) kk = 2048;
#pragma unroll
    for (int s = 0; s < 2; s++) {
        int i = tid + s * 1024;
        if (i >= 2048 - kk) {
            unsigned int t = ~(unsigned int)(sk[i] & 0xFFFFFFFFull);
            g_flags[row * 2048 + t] = 1;
        }
    }
}

// ---------------------------------------------------------------------------
// Kernel C: out = flag ? x : 0, grid-stride over float4s. Reads x only for
// selected frames (~3%); always writes (d_out is poisoned).
// ---------------------------------------------------------------------------
__global__ void output_kernel(const float* __restrict__ x,
                              float* __restrict__ out) {
    const float4* x4 = (const float4*)x;
    float4* o4 = (float4*)out;
    const int stride = gridDim.x * blockDim.x;
    for (int i = blockIdx.x * blockDim.x + threadIdx.x; i < 65536 * 128;
         i += stride) {
        float4 v = make_float4(0.f, 0.f, 0.f, 0.f);
        if (g_flags[i >> 7]) v = x4[i];
        o4[i] = v;
    }
}

extern "C" void kernel_launch(void* const* d_in, const int* in_sizes, int n_in,
                              void* d_out, int out_size) {
    const float* x  = (const float*)d_in[0];
    const float* W1 = (const float*)d_in[1];
    const float* b1 = (const float*)d_in[2];
    const float* W2 = (const float*)d_in[3];
    const float* b2 = (const float*)d_in[4];
    const int* kptr = (n_in >= 6) ? (const int*)d_in[5] : nullptr;

    cudaFuncSetAttribute(score_kernel,
                         cudaFuncAttributeMaxDynamicSharedMemorySize,
                         SMEM_BYTES);
    score_kernel<<<512, 256, SMEM_BYTES>>>(x, W1, b1, W2, b2);
    topk_kernel<<<32, 1024>>>(kptr);
    output_kernel<<<2048, 256>>>(x, (float*)d_out);
}